// round 12
// baseline (speedup 1.0000x reference)
#include <cuda_runtime.h>
#include <cuda_bf16.h>
#include <cuda_fp16.h>
#include <cstdint>

#define MAXN 50000
#define MAXE 900080
#define D1   256
#define H1   4
#define C2   32
#define KA   256          // stored K (single fp16 plane)

// ---------------- scratch (device globals) -----------------------------------
__device__ __half g_h1h[MAXN * D1];            // layer-1 features, fp16
__device__ float g_as1[MAXN * H1];
__device__ float g_ad1[MAXN * H1];
__device__ __half g_h2h[MAXN * C2];            // layer-2 features, fp16
__device__ float g_as2[MAXN];
__device__ float g_ad2[MAXN];
__device__ __half g_xh [MAXN * KA];            // x in fp16 (GEMM1 A)
__device__ __half g_a2h[MAXN * KA];            // layer-2 A (ELU acts, fp16)
__device__ __half g_w1h[D1 * KA];              // W1^T fp16
__device__ __half g_w2h[C2 * KA];              // W2^T fp16
__device__ int g_row[MAXN + 1];
__device__ int g_cur[MAXN];    // INVARIANT: all-zero between kernel_launch calls
__device__ int g_csr[MAXE];

// ---------------- helpers -----------------------------------------------------
__device__ __forceinline__ uint32_t smem_u32(const void* p) {
    uint32_t a;
    asm("{ .reg .u64 t; cvta.to.shared.u64 t, %1; cvt.u32.u64 %0, t; }" : "=r"(a) : "l"(p));
    return a;
}
__device__ __forceinline__ void cp_async16(uint32_t saddr, const void* gptr) {
    asm volatile("cp.async.cg.shared.global [%0], [%1], 16;"
        :: "r"(saddr), "l"(__cvta_generic_to_global(gptr)) : "memory");
}
#define CP_COMMIT asm volatile("cp.async.commit_group;" ::: "memory")
#define CP_WAIT0  asm volatile("cp.async.wait_group 0;" ::: "memory")
#define CP_WAIT1  asm volatile("cp.async.wait_group 1;" ::: "memory")

__device__ __forceinline__ void mma16816h(float* c, const uint32_t* a, uint32_t b0, uint32_t b1) {
    asm volatile("mma.sync.aligned.m16n8k16.row.col.f32.f16.f16.f32 "
        "{%0,%1,%2,%3}, {%4,%5,%6,%7}, {%8,%9}, {%0,%1,%2,%3};"
        : "+f"(c[0]), "+f"(c[1]), "+f"(c[2]), "+f"(c[3])
        : "r"(a[0]), "r"(a[1]), "r"(a[2]), "r"(a[3]), "r"(b0), "r"(b1));
}
__device__ __forceinline__ void ldmatrix4(uint32_t* r, uint32_t addr) {
    asm volatile("ldmatrix.sync.aligned.m8n8.x4.shared.b16 {%0,%1,%2,%3}, [%4];"
        : "=r"(r[0]), "=r"(r[1]), "=r"(r[2]), "=r"(r[3]) : "r"(addr));
}
__device__ __forceinline__ uint32_t pack_h2(float a, float b) {
    __half2 h = __floats2half2_rn(a, b);
    return *(uint32_t*)&h;
}
__device__ __forceinline__ float2 unpack_h2(uint32_t u) {
    return __half22float2(*(__half2*)&u);
}
__device__ __forceinline__ float lrelu_exp(float e) {
    e = (e >= 0.f) ? e : 0.2f * e;
    return __expf(e);
}

// ---------------- prep: fp16 W^T + fp16 x copy --------------------------------
__global__ void prep_wa(const float* __restrict__ x, const float* __restrict__ W1,
                        const float* __restrict__ W2, int Nn) {
    int idx = blockIdx.x * blockDim.x + threadIdx.x;
    if (idx < D1 * D1) {
        int k = idx >> 8, n = idx & 255;
        g_w1h[(size_t)n * KA + k] = __float2half_rn(W1[k * D1 + n]);
        return;
    }
    idx -= D1 * D1;
    if (idx < D1 * C2) {
        int k = idx >> 5, n = idx & 31;
        g_w2h[(size_t)n * KA + k] = __float2half_rn(W2[k * C2 + n]);
        return;
    }
    idx -= D1 * C2;
    if (idx < (Nn * D1) / 4) {
        int row = idx / (D1 / 4), c4 = idx % (D1 / 4);
        float4 v = __ldg((const float4*)(x + (size_t)row * D1) + c4);
        *(uint2*)&g_xh[(size_t)row * KA + 4 * c4] =
            make_uint2(pack_h2(v.x, v.y), pack_h2(v.z, v.w));
    }
}

// ---------------- CSR build (runs on forked stream) ---------------------------
__global__ void csr_count(const int* __restrict__ ei, int E) {
    int i = blockIdx.x * blockDim.x + threadIdx.x;
    if (i < E) atomicAdd(&g_cur[ei[E + i]], 1);
}
__global__ void csr_scan(int Nn) {
    __shared__ int s[1024];
    const int t = threadIdx.x;
    const int chunk = (Nn + 1023) / 1024;
    const int beg = t * chunk;
    const int end = (beg + chunk < Nn) ? beg + chunk : Nn;
    int sum = 0;
    for (int i = beg; i < end; i++) sum += g_cur[i] + 1;   // +1 self loop
    s[t] = sum;
    __syncthreads();
    int run_in = sum;
    for (int d = 1; d < 1024; d <<= 1) {
        int v = (t >= d) ? s[t - d] : 0;
        __syncthreads();
        s[t] += v;
        __syncthreads();
    }
    int run = s[t] - run_in;
    for (int i = beg; i < end; i++) {
        int c = g_cur[i] + 1;
        g_row[i] = run;
        g_cur[i] = run;
        run += c;
    }
    if (end == Nn && beg <= Nn) g_row[Nn] = run;
}
__global__ void csr_scatter(const int* __restrict__ ei, int E, int Nn) {
    int i = blockIdx.x * blockDim.x + threadIdx.x;
    int Etot = E + Nn;
    if (i >= Etot) return;
    int src, dst;
    if (i < E) { src = ei[i]; dst = ei[E + i]; }
    else       { src = dst = i - E; }
    int pos = atomicAdd(&g_cur[dst], 1);
    g_csr[pos] = src;
}

// ---------------- fp16 HMMA GEMM: K=256, ldmatrix, BK=32, 3-stage -------------
// C stored fp16 (g_h1h for layer1, g_h2h for layer2) + fused att epilogue.
template<int BN>
__global__ void __launch_bounds__(256, 2)
gemm_mma(const __half* __restrict__ Ah,
         const __half* __restrict__ Bh,
         __half* __restrict__ Cout,
         const float* __restrict__ att_s, const float* __restrict__ att_d,
         float* __restrict__ out_s, float* __restrict__ out_d, int M)
{
    constexpr int BM = 128, BK = 32, KT = KA / BK;   // 8 k-tiles
    constexpr int LDA = 40;
    constexpr int WN = (BN == 128) ? 64 : 32;
    constexpr int WX = BN / WN, WY = 8 / WX;
    constexpr int MROWS = BM / WY, MT_ = MROWS / 16, NT_ = WN / 8;
    constexpr int NPAIR = NT_ / 2;
    constexpr int NTOT = (BN == 128) ? 256 : 32;
    constexpr int HEADC = WN, NH = NTOT / HEADC;
    constexpr int ABYTES = BM * LDA * 2;
    constexpr int BBYTES = BN * LDA * 2;
    constexpr int STAGE = ABYTES + BBYTES;
    constexpr int ACH = BM * BK / 8;
    constexpr int BCH = BN * BK / 8;

    extern __shared__ char sm[];
    float* s_as = (float*)(sm + 3 * STAGE);
    float* s_ad = s_as + NTOT;

    const int tid = threadIdx.x;
    const int lane = tid & 31, wid = tid >> 5;
    const int wx = wid % WX, wy = wid / WX;
    const int m0 = blockIdx.y * BM;
    const int n0 = blockIdx.x * BN;

    if (tid < NTOT) { s_as[tid] = att_s[tid]; s_ad[tid] = att_d[tid]; }

    const uint32_t smBase = smem_u32(sm);

    auto issue = [&](int kt, int buf) {
        int koff = kt * 32;
        uint32_t aS = smBase + buf * STAGE;
        uint32_t bS = aS + ABYTES;
#pragma unroll
        for (int i = 0; i < ACH / 256; i++) {
            int idx = tid + i * 256;
            int r = idx >> 2, c4 = idx & 3;
            int row = m0 + r; if (row > M - 1) row = M - 1;
            cp_async16(aS + (r * LDA + c4 * 8) * 2,
                       Ah + (size_t)row * KA + koff + c4 * 8);
        }
        if (BCH >= 256) {
#pragma unroll
            for (int i = 0; i < BCH / 256; i++) {
                int idx = tid + i * 256;
                int r = idx >> 2, c4 = idx & 3;
                cp_async16(bS + (r * LDA + c4 * 8) * 2,
                           Bh + (size_t)(n0 + r) * KA + koff + c4 * 8);
            }
        } else if (tid < BCH) {
            int r = tid >> 2, c4 = tid & 3;
            cp_async16(bS + (r * LDA + c4 * 8) * 2,
                       Bh + (size_t)(n0 + r) * KA + koff + c4 * 8);
        }
        CP_COMMIT;
    };

    float acc[MT_][NT_][4];
#pragma unroll
    for (int mt = 0; mt < MT_; mt++)
#pragma unroll
        for (int nt = 0; nt < NT_; nt++)
#pragma unroll
            for (int q = 0; q < 4; q++) acc[mt][nt][q] = 0.f;

    const int aRow = lane & 15;
    const int aCol = (lane & 16) >> 1;
    const int bRow = (lane & 7) + ((lane & 16) >> 1);
    const int bCol = lane & 8;

    issue(0, 0);
    issue(1, 1);
    for (int kt = 0; kt < KT; kt++) {
        if (kt + 2 < KT) { CP_WAIT1; } else { CP_WAIT0; }
        __syncthreads();
        if (kt + 2 < KT) issue(kt + 2, (kt + 2) % 3);
        uint32_t AbU = smBase + (kt % 3) * STAGE;
        uint32_t BbU = AbU + ABYTES;
#pragma unroll
        for (int ks = 0; ks < 2; ks++) {
            const int kq0 = ks * 16;
            uint32_t a[MT_][4];
#pragma unroll
            for (int mt = 0; mt < MT_; mt++)
                ldmatrix4(a[mt], AbU + (((wy * MROWS + mt * 16 + aRow) * LDA + kq0 + aCol) << 1));
#pragma unroll
            for (int np = 0; np < NPAIR; np++) {
                uint32_t b[4];
                ldmatrix4(b, BbU + (((wx * WN + np * 16 + bRow) * LDA + kq0 + bCol) << 1));
#pragma unroll
                for (int mt = 0; mt < MT_; mt++) {
                    mma16816h(acc[mt][2 * np],     a[mt], b[0], b[1]);
                    mma16816h(acc[mt][2 * np + 1], a[mt], b[2], b[3]);
                }
            }
        }
    }

    // epilogue: store C fp16 + fused att dots (warp covers one head)
#pragma unroll
    for (int mt = 0; mt < MT_; mt++) {
        int row = m0 + wy * MROWS + mt * 16 + (lane >> 2);
        float s0 = 0.f, d0 = 0.f, s1 = 0.f, d1 = 0.f;
#pragma unroll
        for (int nt = 0; nt < NT_; nt++) {
            int col = n0 + wx * WN + nt * 8 + (lane & 3) * 2;
            float c0 = acc[mt][nt][0], c1 = acc[mt][nt][1];
            float c2 = acc[mt][nt][2], c3 = acc[mt][nt][3];
            if (row < M)     *(uint32_t*)&Cout[(size_t)row * NTOT + col]       = pack_h2(c0, c1);
            if (row + 8 < M) *(uint32_t*)&Cout[(size_t)(row + 8) * NTOT + col] = pack_h2(c2, c3);
            s0 += c0 * s_as[col] + c1 * s_as[col + 1];
            d0 += c0 * s_ad[col] + c1 * s_ad[col + 1];
            s1 += c2 * s_as[col] + c3 * s_as[col + 1];
            d1 += c2 * s_ad[col] + c3 * s_ad[col + 1];
        }
#pragma unroll
        for (int off = 1; off <= 2; off <<= 1) {
            s0 += __shfl_xor_sync(0xffffffffu, s0, off);
            d0 += __shfl_xor_sync(0xffffffffu, d0, off);
            s1 += __shfl_xor_sync(0xffffffffu, s1, off);
            d1 += __shfl_xor_sync(0xffffffffu, d1, off);
        }
        if ((lane & 3) == 0) {
            int head = (n0 + wx * WN) / HEADC;
            if (row < M)     { out_s[row * NH + head] = s0;       out_d[row * NH + head] = d0; }
            if (row + 8 < M) { out_s[(row + 8) * NH + head] = s1; out_d[(row + 8) * NH + head] = d1; }
        }
    }
}

// ---------------- layer-1 pull: warp per dst node, 2 edges/iter ---------------
// lane owns features 8*lane..8*lane+7 (head lane>>3). p for edge0 on lanes 0-3,
// edge1 on lanes 4-7; den combined at the end.
__global__ void __launch_bounds__(256)
pull1(const float* __restrict__ b1, int Nn) {
    int warp = (blockIdx.x * blockDim.x + threadIdx.x) >> 5;
    int lane = threadIdx.x & 31;
    if (warp >= Nn) return;
    const int d = warp;
    const int base = g_row[d], end = g_row[d + 1];
    if (lane == 0) g_cur[d] = 0;     // restore all-zero invariant

    const int h = lane >> 3;         // head of my 8 features
    float adl = (lane < 8) ? g_ad1[d * H1 + (lane & 3)] : 0.f;
    float acc[8] = {0.f, 0.f, 0.f, 0.f, 0.f, 0.f, 0.f, 0.f};
    float den = 0.f;

    int i = base;
    for (; i + 1 < end; i += 2) {
        int src0 = __ldg(&g_csr[i]);
        int src1 = __ldg(&g_csr[i + 1]);
        float p = 0.f;
        if (lane < 8) {
            int s = (lane < 4) ? src0 : src1;
            p = lrelu_exp(__ldg(&g_as1[s * H1 + (lane & 3)]) + adl);
            den += p;
        }
        float p0 = __shfl_sync(0xffffffffu, p, h);
        float p1 = __shfl_sync(0xffffffffu, p, 4 + h);
        uint4 hv0 = __ldg((const uint4*)(g_h1h + (size_t)src0 * D1) + lane);
        uint4 hv1 = __ldg((const uint4*)(g_h1h + (size_t)src1 * D1) + lane);
        float2 a0 = unpack_h2(hv0.x), a1 = unpack_h2(hv0.y);
        float2 a2 = unpack_h2(hv0.z), a3 = unpack_h2(hv0.w);
        float2 b0 = unpack_h2(hv1.x), b1v = unpack_h2(hv1.y);
        float2 b2v = unpack_h2(hv1.z), b3 = unpack_h2(hv1.w);
        acc[0] += p0 * a0.x + p1 * b0.x;  acc[1] += p0 * a0.y + p1 * b0.y;
        acc[2] += p0 * a1.x + p1 * b1v.x; acc[3] += p0 * a1.y + p1 * b1v.y;
        acc[4] += p0 * a2.x + p1 * b2v.x; acc[5] += p0 * a2.y + p1 * b2v.y;
        acc[6] += p0 * a3.x + p1 * b3.x;  acc[7] += p0 * a3.y + p1 * b3.y;
    }
    if (i < end) {                       // remainder edge
        int src0 = __ldg(&g_csr[i]);
        float p = 0.f;
        if (lane < 4) {
            p = lrelu_exp(__ldg(&g_as1[src0 * H1 + lane]) + adl);
            den += p;
        }
        float p0 = __shfl_sync(0xffffffffu, p, h);
        uint4 hv0 = __ldg((const uint4*)(g_h1h + (size_t)src0 * D1) + lane);
        float2 a0 = unpack_h2(hv0.x), a1 = unpack_h2(hv0.y);
        float2 a2 = unpack_h2(hv0.z), a3 = unpack_h2(hv0.w);
        acc[0] += p0 * a0.x; acc[1] += p0 * a0.y;
        acc[2] += p0 * a1.x; acc[3] += p0 * a1.y;
        acc[4] += p0 * a2.x; acc[5] += p0 * a2.y;
        acc[6] += p0 * a3.x; acc[7] += p0 * a3.y;
    }

    float denT = __shfl_sync(0xffffffffu, den, h) + __shfl_sync(0xffffffffu, den, 4 + h);
    float inv = 1.f / denT;

    const int c = 8 * lane;
    float v[8];
#pragma unroll
    for (int q = 0; q < 8; q++) {
        v[q] = acc[q] * inv + __ldg(&b1[c + q]);
        v[q] = (v[q] > 0.f) ? v[q] : (__expf(v[q]) - 1.f);
    }

    *(uint4*)&g_a2h[(size_t)d * KA + c] = make_uint4(
        pack_h2(v[0], v[1]), pack_h2(v[2], v[3]),
        pack_h2(v[4], v[5]), pack_h2(v[6], v[7]));
}

// ---------------- layer-2 pull: warp per dst, 2 edges/iter (half-warp each) ---
// lanes 0-15 process even-index edges, 16-31 odd-index; each lane covers
// features 2*(lane&15). fp16 h2. Combine halves via shfl_xor(16).
__global__ void __launch_bounds__(256)
pull2(const float* __restrict__ b2, float* __restrict__ out, int Nn) {
    int warp = (blockIdx.x * blockDim.x + threadIdx.x) >> 5;
    int lane = threadIdx.x & 31;
    if (warp >= Nn) return;
    const int d = warp;
    const int base = g_row[d], end = g_row[d + 1];
    const int par = lane >> 4;      // 0: even edges, 1: odd edges
    const int f = lane & 15;        // feature pair index

    float ad = g_ad2[d];
    float accx = 0.f, accy = 0.f, den = 0.f;

    for (int i = base + par; i < end; i += 2) {
        int src = __ldg(&g_csr[i]);
        float p = lrelu_exp(__ldg(&g_as2[src]) + ad);   // broadcast load per half-warp
        den += p;
        uint32_t hv = __ldg((const uint32_t*)(g_h2h + (size_t)src * C2) + f);
        float2 fv = unpack_h2(hv);
        accx += p * fv.x;
        accy += p * fv.y;
    }

    den  += __shfl_xor_sync(0xffffffffu, den, 16);
    accx += __shfl_xor_sync(0xffffffffu, accx, 16);
    accy += __shfl_xor_sync(0xffffffffu, accy, 16);

    if (lane < 16) {
        float inv = 1.f / den;
        int c = 2 * f;
        *(float2*)&out[(size_t)d * C2 + c] =
            make_float2(accx * inv + __ldg(&b2[c]), accy * inv + __ldg(&b2[c + 1]));
    }
}

// ---------------- host orchestration ------------------------------------------
extern "C" void kernel_launch(void* const* d_in, const int* in_sizes, int n_in,
                              void* d_out, int out_size) {
    const float* x     = (const float*)d_in[0];
    const int*   ei    = (const int*)  d_in[1];
    const float* W1    = (const float*)d_in[2];
    const float* asrc1 = (const float*)d_in[3];
    const float* adst1 = (const float*)d_in[4];
    const float* b1    = (const float*)d_in[5];
    const float* W2    = (const float*)d_in[6];
    const float* asrc2 = (const float*)d_in[7];
    const float* adst2 = (const float*)d_in[8];
    const float* b2    = (const float*)d_in[9];
    float* out = (float*)d_out;

    const int Nn = in_sizes[0] / D1;
    const int E  = in_sizes[1] / 2;
    const int Etot = E + Nn;
    const int MT = (Nn + 127) / 128;

    __half *p_xh, *p_a2h, *p_w1h, *p_w2h, *p_h1h, *p_h2h;
    float *p_as1, *p_ad1, *p_as2, *p_ad2;
    cudaGetSymbolAddress((void**)&p_xh,   g_xh);
    cudaGetSymbolAddress((void**)&p_a2h,  g_a2h);
    cudaGetSymbolAddress((void**)&p_w1h,  g_w1h);
    cudaGetSymbolAddress((void**)&p_w2h,  g_w2h);
    cudaGetSymbolAddress((void**)&p_h1h,  g_h1h);
    cudaGetSymbolAddress((void**)&p_h2h,  g_h2h);
    cudaGetSymbolAddress((void**)&p_as1,  g_as1);
    cudaGetSymbolAddress((void**)&p_ad1,  g_ad1);
    cudaGetSymbolAddress((void**)&p_as2,  g_as2);
    cudaGetSymbolAddress((void**)&p_ad2,  g_ad2);

    constexpr int SM1 = 3 * (128 * 40 * 2 + 128 * 40 * 2) + 2 * 256 * 4;
    constexpr int SM2 = 3 * (128 * 40 * 2 + 32 * 40 * 2)  + 2 * 32 * 4;
    cudaFuncSetAttribute(gemm_mma<128>, cudaFuncAttributeMaxDynamicSharedMemorySize, SM1);
    cudaFuncSetAttribute(gemm_mma<32>,  cudaFuncAttributeMaxDynamicSharedMemorySize, SM2);

    // fork: CSR build runs concurrently with prep+gemm1
    cudaStream_t s2;
    cudaStreamCreateWithFlags(&s2, cudaStreamNonBlocking);
    cudaEvent_t evFork, evJoin;
    cudaEventCreateWithFlags(&evFork, cudaEventDisableTiming);
    cudaEventCreateWithFlags(&evJoin, cudaEventDisableTiming);

    cudaEventRecord(evFork, 0);
    cudaStreamWaitEvent(s2, evFork, 0);
    csr_count  <<<(E + 255) / 256, 256, 0, s2>>>(ei, E);
    csr_scan   <<<1, 1024, 0, s2>>>(Nn);
    csr_scatter<<<(Etot + 255) / 256, 256, 0, s2>>>(ei, E, Nn);
    cudaEventRecord(evJoin, s2);

    const int prep_items = D1 * D1 + D1 * C2 + (Nn * D1) / 4;
    prep_wa<<<(prep_items + 255) / 256, 256>>>(x, W1, W2, Nn);
    gemm_mma<128><<<dim3(2, MT), 256, SM1>>>(p_xh, p_w1h, p_h1h, asrc1, adst1, p_as1, p_ad1, Nn);

    cudaStreamWaitEvent(0, evJoin, 0);   // join CSR before pull1

    pull1<<<(Nn + 7) / 8, 256>>>(b1, Nn);
    gemm_mma<32><<<dim3(1, MT), 256, SM2>>>(p_a2h, p_w2h, p_h2h, asrc2, adst2, p_as2, p_ad2, Nn);
    pull2<<<(Nn + 7) / 8, 256>>>(b2, out, Nn);

    cudaEventDestroy(evFork);
    cudaEventDestroy(evJoin);
    cudaStreamDestroy(s2);
}

// round 13
// speedup vs baseline: 1.3418x; 1.3418x over previous
#include <cuda_runtime.h>
#include <cuda_bf16.h>
#include <cuda_fp16.h>
#include <cstdint>

#define MAXN 50000
#define MAXE 900080
#define D1   256
#define H1   4
#define C2   32
#define KA   256          // stored K (single fp16 plane)

// ---------------- scratch (device globals) -----------------------------------
__device__ __half g_h1h[MAXN * D1];            // layer-1 features, fp16
__device__ float g_as1[MAXN * H1];
__device__ float g_ad1[MAXN * H1];
__device__ __half g_h2h[MAXN * C2];            // layer-2 features, fp16
__device__ float g_as2[MAXN];
__device__ float g_ad2[MAXN];
__device__ __half g_xh [MAXN * KA];            // x in fp16 (GEMM1 A)
__device__ __half g_a2h[MAXN * KA];            // layer-2 A (ELU acts, fp16)
__device__ __half g_w1h[D1 * KA];              // W1^T fp16
__device__ __half g_w2h[C2 * KA];              // W2^T fp16
__device__ int g_row[MAXN + 1];
__device__ int g_cur[MAXN];    // INVARIANT: all-zero between kernel_launch calls
__device__ int g_csr[MAXE];

// ---------------- helpers -----------------------------------------------------
__device__ __forceinline__ uint32_t smem_u32(const void* p) {
    uint32_t a;
    asm("{ .reg .u64 t; cvta.to.shared.u64 t, %1; cvt.u32.u64 %0, t; }" : "=r"(a) : "l"(p));
    return a;
}
__device__ __forceinline__ void cp_async16(uint32_t saddr, const void* gptr) {
    asm volatile("cp.async.cg.shared.global [%0], [%1], 16;"
        :: "r"(saddr), "l"(__cvta_generic_to_global(gptr)) : "memory");
}
#define CP_COMMIT asm volatile("cp.async.commit_group;" ::: "memory")
#define CP_WAIT0  asm volatile("cp.async.wait_group 0;" ::: "memory")
#define CP_WAIT1  asm volatile("cp.async.wait_group 1;" ::: "memory")

__device__ __forceinline__ void mma16816h(float* c, const uint32_t* a, uint32_t b0, uint32_t b1) {
    asm volatile("mma.sync.aligned.m16n8k16.row.col.f32.f16.f16.f32 "
        "{%0,%1,%2,%3}, {%4,%5,%6,%7}, {%8,%9}, {%0,%1,%2,%3};"
        : "+f"(c[0]), "+f"(c[1]), "+f"(c[2]), "+f"(c[3])
        : "r"(a[0]), "r"(a[1]), "r"(a[2]), "r"(a[3]), "r"(b0), "r"(b1));
}
__device__ __forceinline__ void ldmatrix4(uint32_t* r, uint32_t addr) {
    asm volatile("ldmatrix.sync.aligned.m8n8.x4.shared.b16 {%0,%1,%2,%3}, [%4];"
        : "=r"(r[0]), "=r"(r[1]), "=r"(r[2]), "=r"(r[3]) : "r"(addr));
}
__device__ __forceinline__ uint32_t pack_h2(float a, float b) {
    __half2 h = __floats2half2_rn(a, b);
    return *(uint32_t*)&h;
}
__device__ __forceinline__ float2 unpack_h2(uint32_t u) {
    return __half22float2(*(__half2*)&u);
}

// ---------------- prep: fp16 W^T + fp16 x copy --------------------------------
__global__ void prep_wa(const float* __restrict__ x, const float* __restrict__ W1,
                        const float* __restrict__ W2, int Nn) {
    int idx = blockIdx.x * blockDim.x + threadIdx.x;
    if (idx < D1 * D1) {
        int k = idx >> 8, n = idx & 255;
        g_w1h[(size_t)n * KA + k] = __float2half_rn(W1[k * D1 + n]);
        return;
    }
    idx -= D1 * D1;
    if (idx < D1 * C2) {
        int k = idx >> 5, n = idx & 31;
        g_w2h[(size_t)n * KA + k] = __float2half_rn(W2[k * C2 + n]);
        return;
    }
    idx -= D1 * C2;
    if (idx < (Nn * D1) / 4) {
        int row = idx / (D1 / 4), c4 = idx % (D1 / 4);
        float4 v = __ldg((const float4*)(x + (size_t)row * D1) + c4);
        *(uint2*)&g_xh[(size_t)row * KA + 4 * c4] =
            make_uint2(pack_h2(v.x, v.y), pack_h2(v.z, v.w));
    }
}

// ---------------- CSR build (runs on forked stream) ---------------------------
__global__ void csr_count(const int* __restrict__ ei, int E) {
    int i = blockIdx.x * blockDim.x + threadIdx.x;
    if (i < E) atomicAdd(&g_cur[ei[E + i]], 1);
}
__global__ void csr_scan(int Nn) {
    __shared__ int s[1024];
    const int t = threadIdx.x;
    const int chunk = (Nn + 1023) / 1024;
    const int beg = t * chunk;
    const int end = (beg + chunk < Nn) ? beg + chunk : Nn;
    int sum = 0;
    for (int i = beg; i < end; i++) sum += g_cur[i] + 1;   // +1 self loop
    s[t] = sum;
    __syncthreads();
    int run_in = sum;
    for (int d = 1; d < 1024; d <<= 1) {
        int v = (t >= d) ? s[t - d] : 0;
        __syncthreads();
        s[t] += v;
        __syncthreads();
    }
    int run = s[t] - run_in;
    for (int i = beg; i < end; i++) {
        int c = g_cur[i] + 1;
        g_row[i] = run;
        g_cur[i] = run;
        run += c;
    }
    if (end == Nn && beg <= Nn) g_row[Nn] = run;
}
__global__ void csr_scatter(const int* __restrict__ ei, int E, int Nn) {
    int i = blockIdx.x * blockDim.x + threadIdx.x;
    int Etot = E + Nn;
    if (i >= Etot) return;
    int src, dst;
    if (i < E) { src = ei[i]; dst = ei[E + i]; }
    else       { src = dst = i - E; }
    int pos = atomicAdd(&g_cur[dst], 1);
    g_csr[pos] = src;
}

// ---------------- fp16 HMMA GEMM: K=256, ldmatrix, BK=32, 3-stage -------------
// C stored fp16 (g_h1h for layer1, g_h2h for layer2) + fused att epilogue.
template<int BN>
__global__ void __launch_bounds__(256, 2)
gemm_mma(const __half* __restrict__ Ah,
         const __half* __restrict__ Bh,
         __half* __restrict__ Cout,
         const float* __restrict__ att_s, const float* __restrict__ att_d,
         float* __restrict__ out_s, float* __restrict__ out_d, int M)
{
    constexpr int BM = 128, BK = 32, KT = KA / BK;   // 8 k-tiles
    constexpr int LDA = 40;
    constexpr int WN = (BN == 128) ? 64 : 32;
    constexpr int WX = BN / WN, WY = 8 / WX;
    constexpr int MROWS = BM / WY, MT_ = MROWS / 16, NT_ = WN / 8;
    constexpr int NPAIR = NT_ / 2;
    constexpr int NTOT = (BN == 128) ? 256 : 32;
    constexpr int HEADC = WN, NH = NTOT / HEADC;
    constexpr int ABYTES = BM * LDA * 2;
    constexpr int BBYTES = BN * LDA * 2;
    constexpr int STAGE = ABYTES + BBYTES;
    constexpr int ACH = BM * BK / 8;
    constexpr int BCH = BN * BK / 8;

    extern __shared__ char sm[];
    float* s_as = (float*)(sm + 3 * STAGE);
    float* s_ad = s_as + NTOT;

    const int tid = threadIdx.x;
    const int lane = tid & 31, wid = tid >> 5;
    const int wx = wid % WX, wy = wid / WX;
    const int m0 = blockIdx.y * BM;
    const int n0 = blockIdx.x * BN;

    if (tid < NTOT) { s_as[tid] = att_s[tid]; s_ad[tid] = att_d[tid]; }

    const uint32_t smBase = smem_u32(sm);

    auto issue = [&](int kt, int buf) {
        int koff = kt * 32;
        uint32_t aS = smBase + buf * STAGE;
        uint32_t bS = aS + ABYTES;
#pragma unroll
        for (int i = 0; i < ACH / 256; i++) {
            int idx = tid + i * 256;
            int r = idx >> 2, c4 = idx & 3;
            int row = m0 + r; if (row > M - 1) row = M - 1;
            cp_async16(aS + (r * LDA + c4 * 8) * 2,
                       Ah + (size_t)row * KA + koff + c4 * 8);
        }
        if (BCH >= 256) {
#pragma unroll
            for (int i = 0; i < BCH / 256; i++) {
                int idx = tid + i * 256;
                int r = idx >> 2, c4 = idx & 3;
                cp_async16(bS + (r * LDA + c4 * 8) * 2,
                           Bh + (size_t)(n0 + r) * KA + koff + c4 * 8);
            }
        } else if (tid < BCH) {
            int r = tid >> 2, c4 = tid & 3;
            cp_async16(bS + (r * LDA + c4 * 8) * 2,
                       Bh + (size_t)(n0 + r) * KA + koff + c4 * 8);
        }
        CP_COMMIT;
    };

    float acc[MT_][NT_][4];
#pragma unroll
    for (int mt = 0; mt < MT_; mt++)
#pragma unroll
        for (int nt = 0; nt < NT_; nt++)
#pragma unroll
            for (int q = 0; q < 4; q++) acc[mt][nt][q] = 0.f;

    const int aRow = lane & 15;
    const int aCol = (lane & 16) >> 1;
    const int bRow = (lane & 7) + ((lane & 16) >> 1);
    const int bCol = lane & 8;

    issue(0, 0);
    issue(1, 1);
    for (int kt = 0; kt < KT; kt++) {
        if (kt + 2 < KT) { CP_WAIT1; } else { CP_WAIT0; }
        __syncthreads();
        if (kt + 2 < KT) issue(kt + 2, (kt + 2) % 3);
        uint32_t AbU = smBase + (kt % 3) * STAGE;
        uint32_t BbU = AbU + ABYTES;
#pragma unroll
        for (int ks = 0; ks < 2; ks++) {
            const int kq0 = ks * 16;
            uint32_t a[MT_][4];
#pragma unroll
            for (int mt = 0; mt < MT_; mt++)
                ldmatrix4(a[mt], AbU + (((wy * MROWS + mt * 16 + aRow) * LDA + kq0 + aCol) << 1));
#pragma unroll
            for (int np = 0; np < NPAIR; np++) {
                uint32_t b[4];
                ldmatrix4(b, BbU + (((wx * WN + np * 16 + bRow) * LDA + kq0 + bCol) << 1));
#pragma unroll
                for (int mt = 0; mt < MT_; mt++) {
                    mma16816h(acc[mt][2 * np],     a[mt], b[0], b[1]);
                    mma16816h(acc[mt][2 * np + 1], a[mt], b[2], b[3]);
                }
            }
        }
    }

    // epilogue: store C fp16 + fused att dots (warp covers one head)
#pragma unroll
    for (int mt = 0; mt < MT_; mt++) {
        int row = m0 + wy * MROWS + mt * 16 + (lane >> 2);
        float s0 = 0.f, d0 = 0.f, s1 = 0.f, d1 = 0.f;
#pragma unroll
        for (int nt = 0; nt < NT_; nt++) {
            int col = n0 + wx * WN + nt * 8 + (lane & 3) * 2;
            float c0 = acc[mt][nt][0], c1 = acc[mt][nt][1];
            float c2 = acc[mt][nt][2], c3 = acc[mt][nt][3];
            if (row < M)     *(uint32_t*)&Cout[(size_t)row * NTOT + col]       = pack_h2(c0, c1);
            if (row + 8 < M) *(uint32_t*)&Cout[(size_t)(row + 8) * NTOT + col] = pack_h2(c2, c3);
            s0 += c0 * s_as[col] + c1 * s_as[col + 1];
            d0 += c0 * s_ad[col] + c1 * s_ad[col + 1];
            s1 += c2 * s_as[col] + c3 * s_as[col + 1];
            d1 += c2 * s_ad[col] + c3 * s_ad[col + 1];
        }
#pragma unroll
        for (int off = 1; off <= 2; off <<= 1) {
            s0 += __shfl_xor_sync(0xffffffffu, s0, off);
            d0 += __shfl_xor_sync(0xffffffffu, d0, off);
            s1 += __shfl_xor_sync(0xffffffffu, s1, off);
            d1 += __shfl_xor_sync(0xffffffffu, d1, off);
        }
        if ((lane & 3) == 0) {
            int head = (n0 + wx * WN) / HEADC;
            if (row < M)     { out_s[row * NH + head] = s0;       out_d[row * NH + head] = d0; }
            if (row + 8 < M) { out_s[(row + 8) * NH + head] = s1; out_d[(row + 8) * NH + head] = d1; }
        }
    }
}

// ---------------- layer-1 pull: warp per dst node (R11 structure) -------------
// lane owns features 8*lane..8*lane+7 (head lane>>3): ONE uint4 per edge,
// csr index software-prefetched one iteration ahead.
__global__ void __launch_bounds__(256)
pull1(const float* __restrict__ b1, int Nn) {
    int warp = (blockIdx.x * blockDim.x + threadIdx.x) >> 5;
    int lane = threadIdx.x & 31;
    if (warp >= Nn) return;
    const int d = warp;
    const int base = g_row[d], end = g_row[d + 1];
    if (lane == 0) g_cur[d] = 0;     // restore all-zero invariant

    const int h = lane >> 3;         // head of my 8 features
    float adl = (lane < H1) ? g_ad1[d * H1 + lane] : 0.f;
    float acc[8] = {0.f, 0.f, 0.f, 0.f, 0.f, 0.f, 0.f, 0.f};
    float den = 0.f;

    int src_next = g_csr[base];
    for (int i = base; i < end; i++) {
        int src = src_next;
        if (i + 1 < end) src_next = g_csr[i + 1];
        float p = 0.f;
        if (lane < H1) {
            float e = __ldg(&g_as1[src * H1 + lane]) + adl;
            e = (e >= 0.f) ? e : 0.2f * e;
            p = __expf(e);
            den += p;
        }
        float ph = __shfl_sync(0xffffffffu, p, h);
        uint4 hv = __ldg((const uint4*)(g_h1h + (size_t)src * D1) + lane);
        float2 f0 = unpack_h2(hv.x), f1 = unpack_h2(hv.y);
        float2 f2 = unpack_h2(hv.z), f3 = unpack_h2(hv.w);
        acc[0] += ph * f0.x; acc[1] += ph * f0.y;
        acc[2] += ph * f1.x; acc[3] += ph * f1.y;
        acc[4] += ph * f2.x; acc[5] += ph * f2.y;
        acc[6] += ph * f3.x; acc[7] += ph * f3.y;
    }

    float inv = 1.f / __shfl_sync(0xffffffffu, den, h);

    const int c = 8 * lane;
    float v[8];
#pragma unroll
    for (int q = 0; q < 8; q++) {
        v[q] = acc[q] * inv + __ldg(&b1[c + q]);
        v[q] = (v[q] > 0.f) ? v[q] : (__expf(v[q]) - 1.f);
    }

    *(uint4*)&g_a2h[(size_t)d * KA + c] = make_uint4(
        pack_h2(v[0], v[1]), pack_h2(v[2], v[3]),
        pack_h2(v[4], v[5]), pack_h2(v[6], v[7]));
}

// ---------------- layer-2 pull: warp per dst node (R11 structure, fp16 h2) ----
// lane owns feature pair 2*(lane&15); lanes 16-31 mirror 0-15 (same loads hit
// the same lines); lanes 0-15 write the final float2.
__global__ void __launch_bounds__(256)
pull2(const float* __restrict__ b2, float* __restrict__ out, int Nn) {
    int warp = (blockIdx.x * blockDim.x + threadIdx.x) >> 5;
    int lane = threadIdx.x & 31;
    if (warp >= Nn) return;
    const int d = warp;
    const int base = g_row[d], end = g_row[d + 1];
    const int f = lane & 15;

    float ad = g_ad2[d];
    float accx = 0.f, accy = 0.f, den = 0.f;

    int src_next = g_csr[base];
    for (int i = base; i < end; i++) {
        int src = src_next;
        if (i + 1 < end) src_next = g_csr[i + 1];
        float p = 0.f;
        if (lane == 0) {
            float e = __ldg(&g_as2[src]) + ad;
            e = (e >= 0.f) ? e : 0.2f * e;
            p = __expf(e);
        }
        p = __shfl_sync(0xffffffffu, p, 0);
        den += p;
        uint32_t hv = __ldg((const uint32_t*)(g_h2h + (size_t)src * C2) + f);
        float2 fv = unpack_h2(hv);
        accx += p * fv.x;
        accy += p * fv.y;
    }
    if (lane < 16) {
        float inv = 1.f / den;
        int c = 2 * f;
        *(float2*)&out[(size_t)d * C2 + c] =
            make_float2(accx * inv + __ldg(&b2[c]), accy * inv + __ldg(&b2[c + 1]));
    }
}

// ---------------- host orchestration ------------------------------------------
extern "C" void kernel_launch(void* const* d_in, const int* in_sizes, int n_in,
                              void* d_out, int out_size) {
    const float* x     = (const float*)d_in[0];
    const int*   ei    = (const int*)  d_in[1];
    const float* W1    = (const float*)d_in[2];
    const float* asrc1 = (const float*)d_in[3];
    const float* adst1 = (const float*)d_in[4];
    const float* b1    = (const float*)d_in[5];
    const float* W2    = (const float*)d_in[6];
    const float* asrc2 = (const float*)d_in[7];
    const float* adst2 = (const float*)d_in[8];
    const float* b2    = (const float*)d_in[9];
    float* out = (float*)d_out;

    const int Nn = in_sizes[0] / D1;
    const int E  = in_sizes[1] / 2;
    const int Etot = E + Nn;
    const int MT = (Nn + 127) / 128;

    __half *p_xh, *p_a2h, *p_w1h, *p_w2h, *p_h1h, *p_h2h;
    float *p_as1, *p_ad1, *p_as2, *p_ad2;
    cudaGetSymbolAddress((void**)&p_xh,   g_xh);
    cudaGetSymbolAddress((void**)&p_a2h,  g_a2h);
    cudaGetSymbolAddress((void**)&p_w1h,  g_w1h);
    cudaGetSymbolAddress((void**)&p_w2h,  g_w2h);
    cudaGetSymbolAddress((void**)&p_h1h,  g_h1h);
    cudaGetSymbolAddress((void**)&p_h2h,  g_h2h);
    cudaGetSymbolAddress((void**)&p_as1,  g_as1);
    cudaGetSymbolAddress((void**)&p_ad1,  g_ad1);
    cudaGetSymbolAddress((void**)&p_as2,  g_as2);
    cudaGetSymbolAddress((void**)&p_ad2,  g_ad2);

    constexpr int SM1 = 3 * (128 * 40 * 2 + 128 * 40 * 2) + 2 * 256 * 4;
    constexpr int SM2 = 3 * (128 * 40 * 2 + 32 * 40 * 2)  + 2 * 32 * 4;
    cudaFuncSetAttribute(gemm_mma<128>, cudaFuncAttributeMaxDynamicSharedMemorySize, SM1);
    cudaFuncSetAttribute(gemm_mma<32>,  cudaFuncAttributeMaxDynamicSharedMemorySize, SM2);

    // fork: CSR build runs concurrently with prep+gemm1
    cudaStream_t s2;
    cudaStreamCreateWithFlags(&s2, cudaStreamNonBlocking);
    cudaEvent_t evFork, evJoin;
    cudaEventCreateWithFlags(&evFork, cudaEventDisableTiming);
    cudaEventCreateWithFlags(&evJoin, cudaEventDisableTiming);

    cudaEventRecord(evFork, 0);
    cudaStreamWaitEvent(s2, evFork, 0);
    csr_count  <<<(E + 255) / 256, 256, 0, s2>>>(ei, E);
    csr_scan   <<<1, 1024, 0, s2>>>(Nn);
    csr_scatter<<<(Etot + 255) / 256, 256, 0, s2>>>(ei, E, Nn);
    cudaEventRecord(evJoin, s2);

    const int prep_items = D1 * D1 + D1 * C2 + (Nn * D1) / 4;
    prep_wa<<<(prep_items + 255) / 256, 256>>>(x, W1, W2, Nn);
    gemm_mma<128><<<dim3(2, MT), 256, SM1>>>(p_xh, p_w1h, p_h1h, asrc1, adst1, p_as1, p_ad1, Nn);

    cudaStreamWaitEvent(0, evJoin, 0);   // join CSR before pull1

    pull1<<<(Nn + 7) / 8, 256>>>(b1, Nn);
    gemm_mma<32><<<dim3(1, MT), 256, SM2>>>(p_a2h, p_w2h, p_h2h, asrc2, adst2, p_as2, p_ad2, Nn);
    pull2<<<(Nn + 7) / 8, 256>>>(b2, out, Nn);

    cudaEventDestroy(evFork);
    cudaEventDestroy(evJoin);
    cudaStreamDestroy(s2);
}